// round 17
// baseline (speedup 1.0000x reference)
#include <cuda_runtime.h>
#include <cuda_bf16.h>
#include <cstdint>

// ---------------- problem constants ----------------
#define NN   65536
#define MM   65536
#define HH   128
#define BB   64
#define OUTD 2
#define ALPHA 0.9f
#define EMAX (1 << 20)
#define GEMM_GRID 296          // 148 SMs x 2 CTAs (persistent)

// ---------------- device scratch ----------------
__device__ float g_base_x0 [(size_t)NN * HH];
__device__ float g_base_x1 [(size_t)NN * HH];
__device__ float g_base_agg[(size_t)NN * HH];
__device__ float g_local_x0[(size_t)MM * HH];
__device__ float g_local_x1[(size_t)MM * HH];
__device__ float g_local_agg[(size_t)MM * HH];
__device__ float g_sub[BB * HH];
__device__ float g_cnt[BB];

// bf16 mirrors of the activation buffers (gather operand for spmm)
__device__ __nv_bfloat16 g_base_xb0 [(size_t)NN * HH];
__device__ __nv_bfloat16 g_base_xb1 [(size_t)NN * HH];
__device__ __nv_bfloat16 g_local_xb0[(size_t)MM * HH];
__device__ __nv_bfloat16 g_local_xb1[(size_t)MM * HH];

__device__ int   g_csr_cnt [2][NN];
__device__ int   g_csr_ptr [2][NN + 1];
__device__ int   g_csr_fill[2][NN];
__device__ int   g_csr_src [2][EMAX];
__device__ float g_csr_w   [2][EMAX];
__device__ int   g_chunks  [2][256];

// ---------------- persistent GEMM: C = relu(A' @ W + bias), dual fp32+bf16 output ----------------
#define GEMM_SMEM ((128 * 64 + 128 * 128) * sizeof(float))   // 98304 B

__device__ __forceinline__ void ffma2(unsigned long long& d,
                                      unsigned long long a,
                                      unsigned long long b)
{
    asm("fma.rn.f32x2 %0, %1, %2, %0;" : "+l"(d) : "l"(a), "l"(b));
}

__device__ __forceinline__ unsigned long long dup_reg(float x)
{
    unsigned long long r;
    asm("mov.b64 %0, {%1, %1};" : "=l"(r) : "r"(__float_as_uint(x)));
    return r;
}

__device__ __forceinline__ uint32_t pack_bf16(float a, float b)
{
    __nv_bfloat162 h = __floats2bfloat162_rn(a, b);
    return *(uint32_t*)&h;
}

template<bool MIX>
__global__ void __launch_bounds__(256, 2)
gemm128_bias_relu(const float* __restrict__ A,
                  const float* __restrict__ W,
                  const float* __restrict__ bias,
                  float* __restrict__ C,
                  __nv_bfloat16* __restrict__ Cb,
                  const float* __restrict__ BX,
                  const int* __restrict__ c2o,
                  int n_tiles)
{
    extern __shared__ float smem[];
    float* As = smem;                // [128][64]   As[k][r ^ swz(k)]
    float* Ws = smem + 128 * 64;     // [128][128]  Ws[k][col]

    const int tid = threadIdx.x;

    // ---- stage W ONCE per persistent CTA ----
    {
        const float4* W4  = (const float4*)W;
        float4*       Ws4 = (float4*)Ws;
        #pragma unroll
        for (int i = 0; i < 16; i++) Ws4[tid + 256 * i] = W4[tid + 256 * i];
    }

    const int j  = tid & 15;
    const int tr = (tid >> 4) * 4;
    const int c0 = 4 * j;
    const int c1 = 64 + 4 * j;
    float4 bv0 = *(const float4*)&bias[c0];
    float4 bv1 = *(const float4*)&bias[c1];

    for (int t = blockIdx.x; t < n_tiles; t += GEMM_GRID) {
        const int row0 = t * 64;

        {
            const float4* A4 = (const float4*)(A + (size_t)row0 * HH);
            #pragma unroll
            for (int i = 0; i < 8; i++) {
                int idx = tid + 256 * i;      // = r*32 + k4
                int r   = idx >> 5;           // 0..63
                int k4  = idx & 31;
                float4 v = A4[idx];
                if (MIX) {
                    int o = __ldg(&c2o[row0 + r]);
                    float4 b = *(const float4*)&BX[(size_t)o * HH + k4 * 4];
                    v.x = ALPHA * v.x + (1.0f - ALPHA) * b.x;
                    v.y = ALPHA * v.y + (1.0f - ALPHA) * b.y;
                    v.z = ALPHA * v.z + (1.0f - ALPHA) * b.z;
                    v.w = ALPHA * v.w + (1.0f - ALPHA) * b.w;
                }
                int rs = r ^ (4 * (k4 & 15));
                As[(4 * k4 + 0) * 64 + rs] = v.x;
                As[(4 * k4 + 1) * 64 + rs] = v.y;
                As[(4 * k4 + 2) * 64 + rs] = v.z;
                As[(4 * k4 + 3) * 64 + rs] = v.w;
            }
        }
        __syncthreads();

        unsigned long long acc2[4][4];
        #pragma unroll
        for (int m = 0; m < 4; m++)
            #pragma unroll
            for (int p = 0; p < 4; p++) acc2[m][p] = 0ull;

        #pragma unroll 4
        for (int k = 0; k < 128; k++) {
            const int ab = tr ^ (4 * ((k >> 2) & 15));
            float4 a0 = *(const float4*)&As[k * 64 + ab];
            ulonglong2 w0 = *(const ulonglong2*)&Ws[k * 128 + c0];
            ulonglong2 w1 = *(const ulonglong2*)&Ws[k * 128 + c1];

            unsigned long long a2[4];
            a2[0] = dup_reg(a0.x); a2[1] = dup_reg(a0.y);
            a2[2] = dup_reg(a0.z); a2[3] = dup_reg(a0.w);
            unsigned long long wv[4] = {w0.x, w0.y, w1.x, w1.y};

            #pragma unroll
            for (int m = 0; m < 4; m++)
                #pragma unroll
                for (int p = 0; p < 4; p++)
                    ffma2(acc2[m][p], a2[m], wv[p]);
        }

        #pragma unroll
        for (int m = 0; m < 4; m++) {
            float2 p0 = *(float2*)&acc2[m][0];
            float2 p1 = *(float2*)&acc2[m][1];
            float2 p2 = *(float2*)&acc2[m][2];
            float2 p3 = *(float2*)&acc2[m][3];
            float4 o0, o1;
            o0.x = fmaxf(p0.x + bv0.x, 0.f);
            o0.y = fmaxf(p0.y + bv0.y, 0.f);
            o0.z = fmaxf(p1.x + bv0.z, 0.f);
            o0.w = fmaxf(p1.y + bv0.w, 0.f);
            o1.x = fmaxf(p2.x + bv1.x, 0.f);
            o1.y = fmaxf(p2.y + bv1.y, 0.f);
            o1.z = fmaxf(p3.x + bv1.z, 0.f);
            o1.w = fmaxf(p3.y + bv1.w, 0.f);
            const size_t rb = (size_t)(row0 + tr + m) * HH;
            *(float4*)&C[rb + c0] = o0;
            *(float4*)&C[rb + c1] = o1;
            uint2 u0, u1;
            u0.x = pack_bf16(o0.x, o0.y); u0.y = pack_bf16(o0.z, o0.w);
            u1.x = pack_bf16(o1.x, o1.y); u1.y = pack_bf16(o1.z, o1.w);
            *(uint2*)&Cb[rb + c0] = u0;
            *(uint2*)&Cb[rb + c1] = u1;
        }
        __syncthreads();
    }
}

// ---------------- CSR build, fused across both graphs ----------------
__global__ void hist2_kernel(const int* __restrict__ dst_b, int E,
                             const int* __restrict__ dst_l, int EL,
                             int* __restrict__ cnt)
{
    int e = blockIdx.x * blockDim.x + threadIdx.x;
    if (e < E)            atomicAdd(&cnt[dst_b[e]], 1);
    else if (e < E + EL)  atomicAdd(&cnt[NN + dst_l[e - E]], 1);
}

__global__ void chunksum_kernel(const int* __restrict__ cnt, int* __restrict__ chunks)
{
    const int tid = threadIdx.x, lane = tid & 31, w = tid >> 5;
    __shared__ int wsum[8];
    int v = cnt[blockIdx.x * 256 + tid];
    #pragma unroll
    for (int off = 16; off > 0; off >>= 1) v += __shfl_down_sync(0xffffffffu, v, off);
    if (lane == 0) wsum[w] = v;
    __syncthreads();
    if (tid == 0) {
        int s = 0;
        #pragma unroll
        for (int i = 0; i < 8; i++) s += wsum[i];
        chunks[blockIdx.x] = s;
    }
}

__global__ void scan2_kernel(int* __restrict__ chunks,
                             int* __restrict__ ptr_b, int* __restrict__ ptr_l, int n)
{
    const int g   = blockIdx.x;
    const int tid = threadIdx.x, lane = tid & 31, w = tid >> 5;
    int* ch = chunks + g * 256;
    __shared__ int wsum[8];
    int v = ch[tid];
    int inc = v;
    #pragma unroll
    for (int off = 1; off < 32; off <<= 1) {
        int t = __shfl_up_sync(0xffffffffu, inc, off);
        if (lane >= off) inc += t;
    }
    if (lane == 31) wsum[w] = inc;
    __syncthreads();
    if (w == 0 && lane < 8) {
        int s = wsum[lane];
        #pragma unroll
        for (int off = 1; off < 8; off <<= 1) {
            int t = __shfl_up_sync(0x000000ffu, s, off);
            if (lane >= off) s += t;
        }
        wsum[lane] = s;
    }
    __syncthreads();
    int excl = inc - v + (w > 0 ? wsum[w - 1] : 0);
    ch[tid] = excl;
    if (tid == 255) {
        if (g == 0) ptr_b[n] = excl + v; else ptr_l[n] = excl + v;
    }
}

__global__ void write_ptr2_kernel(const int* __restrict__ cnt,
                                  const int* __restrict__ chunks,
                                  int* __restrict__ ptr_b,
                                  int* __restrict__ ptr_l)
{
    const int tid = threadIdx.x, lane = tid & 31, w = tid >> 5;
    __shared__ int wsum[8];
    const int gid = blockIdx.x * 256 + tid;
    int v = cnt[gid];
    int inc = v;
    #pragma unroll
    for (int off = 1; off < 32; off <<= 1) {
        int t = __shfl_up_sync(0xffffffffu, inc, off);
        if (lane >= off) inc += t;
    }
    if (lane == 31) wsum[w] = inc;
    __syncthreads();
    if (w == 0 && lane < 8) {
        int s = wsum[lane];
        #pragma unroll
        for (int off = 1; off < 8; off <<= 1) {
            int t = __shfl_up_sync(0x000000ffu, s, off);
            if (lane >= off) s += t;
        }
        wsum[lane] = s;
    }
    __syncthreads();
    int val = inc - v + (w > 0 ? wsum[w - 1] : 0) + chunks[blockIdx.x];
    if (gid < NN) ptr_b[gid] = val;
    else          ptr_l[gid - NN] = val;
}

__global__ void scatter2_kernel(const int* __restrict__ ei,  int E,
                                const float* __restrict__ ew,
                                const int* __restrict__ lei, int EL,
                                const float* __restrict__ lev,
                                const int* __restrict__ ptr_b, int* __restrict__ fill_b,
                                int* __restrict__ src_b, float* __restrict__ w_b,
                                const int* __restrict__ ptr_l, int* __restrict__ fill_l,
                                int* __restrict__ src_l, float* __restrict__ w_l)
{
    int e = blockIdx.x * blockDim.x + threadIdx.x;
    if (e < E) {
        int d = ei[E + e];
        int pos = ptr_b[d] + atomicAdd(&fill_b[d], 1);
        src_b[pos] = ei[e];
        w_b[pos]   = ew[e];
    } else if (e < E + EL) {
        int ee = e - E;
        int d = lei[EL + ee];
        int pos = ptr_l[d] + atomicAdd(&fill_l[d], 1);
        src_l[pos] = lei[ee];
        w_l[pos]   = lev[ee];
    }
}

// ---------------- SpMM over CSR: HALF-WARP per row, bf16 gather / fp32 accumulate ----------------
// Lanes 0-15 -> row 2w, lanes 16-31 -> row 2w+1. Each lane loads uint4 = 8 bf16.
// 2-edge unroll x 2 rows = 4 independent gather chains per warp.
__global__ void __launch_bounds__(256, 8)
spmm_csr(const __nv_bfloat16* __restrict__ X,
         const int* __restrict__ ptr,
         const int* __restrict__ csrc,
         const float* __restrict__ cw,
         float* __restrict__ Y, int n)
{
    const int lane = threadIdx.x & 31;
    const int hl   = lane & 15;           // lane within half-warp
    const int half = lane >> 4;           // 0 or 1
    const int warp = (blockIdx.x * blockDim.x + threadIdx.x) >> 5;
    const int row  = warp * 2 + half;
    if (row >= n) return;

    const int beg = ptr[row];
    const int end = ptr[row + 1];

    float acc0[8], acc1[8];
    #pragma unroll
    for (int q = 0; q < 8; q++) { acc0[q] = 0.f; acc1[q] = 0.f; }

    const size_t lofs = (size_t)hl * 8;   // bf16 offset within row

    int i = beg;
    for (; i + 1 < end; i += 2) {
        int   s0 = csrc[i];     float w0 = cw[i];
        int   s1 = csrc[i + 1]; float w1 = cw[i + 1];
        uint4 v0 = *(const uint4*)&X[(size_t)s0 * HH + lofs];
        uint4 v1 = *(const uint4*)&X[(size_t)s1 * HH + lofs];
        float2 a0 = __bfloat1622float2(*(__nv_bfloat162*)&v0.x);
        float2 a1 = __bfloat1622float2(*(__nv_bfloat162*)&v0.y);
        float2 a2 = __bfloat1622float2(*(__nv_bfloat162*)&v0.z);
        float2 a3 = __bfloat1622float2(*(__nv_bfloat162*)&v0.w);
        float2 b0 = __bfloat1622float2(*(__nv_bfloat162*)&v1.x);
        float2 b1 = __bfloat1622float2(*(__nv_bfloat162*)&v1.y);
        float2 b2 = __bfloat1622float2(*(__nv_bfloat162*)&v1.z);
        float2 b3 = __bfloat1622float2(*(__nv_bfloat162*)&v1.w);
        acc0[0] = fmaf(w0, a0.x, acc0[0]); acc0[1] = fmaf(w0, a0.y, acc0[1]);
        acc0[2] = fmaf(w0, a1.x, acc0[2]); acc0[3] = fmaf(w0, a1.y, acc0[3]);
        acc0[4] = fmaf(w0, a2.x, acc0[4]); acc0[5] = fmaf(w0, a2.y, acc0[5]);
        acc0[6] = fmaf(w0, a3.x, acc0[6]); acc0[7] = fmaf(w0, a3.y, acc0[7]);
        acc1[0] = fmaf(w1, b0.x, acc1[0]); acc1[1] = fmaf(w1, b0.y, acc1[1]);
        acc1[2] = fmaf(w1, b1.x, acc1[2]); acc1[3] = fmaf(w1, b1.y, acc1[3]);
        acc1[4] = fmaf(w1, b2.x, acc1[4]); acc1[5] = fmaf(w1, b2.y, acc1[5]);
        acc1[6] = fmaf(w1, b3.x, acc1[6]); acc1[7] = fmaf(w1, b3.y, acc1[7]);
    }
    if (i < end) {
        int s = csrc[i]; float w = cw[i];
        uint4 v = *(const uint4*)&X[(size_t)s * HH + lofs];
        float2 a0 = __bfloat1622float2(*(__nv_bfloat162*)&v.x);
        float2 a1 = __bfloat1622float2(*(__nv_bfloat162*)&v.y);
        float2 a2 = __bfloat1622float2(*(__nv_bfloat162*)&v.z);
        float2 a3 = __bfloat1622float2(*(__nv_bfloat162*)&v.w);
        acc0[0] = fmaf(w, a0.x, acc0[0]); acc0[1] = fmaf(w, a0.y, acc0[1]);
        acc0[2] = fmaf(w, a1.x, acc0[2]); acc0[3] = fmaf(w, a1.y, acc0[3]);
        acc0[4] = fmaf(w, a2.x, acc0[4]); acc0[5] = fmaf(w, a2.y, acc0[5]);
        acc0[6] = fmaf(w, a3.x, acc0[6]); acc0[7] = fmaf(w, a3.y, acc0[7]);
    }

    float* yp = &Y[(size_t)row * HH + hl * 8];
    float4 o0, o1;
    o0.x = acc0[0] + acc1[0]; o0.y = acc0[1] + acc1[1];
    o0.z = acc0[2] + acc1[2]; o0.w = acc0[3] + acc1[3];
    o1.x = acc0[4] + acc1[4]; o1.y = acc0[5] + acc1[5];
    o1.z = acc0[6] + acc1[6]; o1.w = acc0[7] + acc1[7];
    ((float4*)yp)[0] = o0;
    ((float4*)yp)[1] = o1;
}

// ---------------- pooling ----------------
__global__ void pool_kernel(const float* __restrict__ lx,
                            const int* __restrict__ midx,
                            const int* __restrict__ mgid,
                            float* __restrict__ gsub,
                            float* __restrict__ gcnt,
                            int K, int entries_per_block)
{
    __shared__ float acc[BB * HH];
    __shared__ float cnt[BB];
    const int tid = threadIdx.x;
    for (int i = tid; i < BB * HH; i += blockDim.x) acc[i] = 0.f;
    if (tid < BB) cnt[tid] = 0.f;
    __syncthreads();

    const int warp = tid >> 5;
    const int lane = tid & 31;
    const int base = blockIdx.x * entries_per_block;
    const int end  = min(base + entries_per_block, K);
    for (int k = base + warp; k < end; k += (int)(blockDim.x >> 5)) {
        int idx = midx[k];
        int g   = mgid[k];
        float4 v = *(const float4*)&lx[(size_t)idx * HH + lane * 4];
        atomicAdd(&acc[g * HH + lane * 4 + 0], v.x);
        atomicAdd(&acc[g * HH + lane * 4 + 1], v.y);
        atomicAdd(&acc[g * HH + lane * 4 + 2], v.z);
        atomicAdd(&acc[g * HH + lane * 4 + 3], v.w);
        if (lane == 0) atomicAdd(&cnt[g], 1.f);
    }
    __syncthreads();

    for (int i = tid; i < BB * HH; i += blockDim.x)
        if (acc[i] != 0.f) atomicAdd(&gsub[i], acc[i]);
    if (tid < BB && cnt[tid] != 0.f) atomicAdd(&gcnt[tid], cnt[tid]);
}

__global__ void final_kernel(const float* __restrict__ gsub,
                             const float* __restrict__ gcnt,
                             const float* __restrict__ Wp,
                             const float* __restrict__ bp,
                             float* __restrict__ out)
{
    int t = threadIdx.x;
    if (t >= BB * OUTD) return;
    int b = t >> 1, o = t & 1;
    float c = fmaxf(gcnt[b], 1.f);
    float s = 0.f;
    #pragma unroll 8
    for (int h = 0; h < HH; h++) s = fmaf(gsub[b * HH + h], Wp[h * OUTD + o], s);
    out[t] = s / c + bp[o];
}

// ---------------- persistent stream/event resources ----------------
static cudaStream_t g_s1 = nullptr;
static cudaEvent_t  g_ev[8];

// ---------------- host orchestration: two-stream fork/join ----------------
extern "C" void kernel_launch(void* const* d_in, const int* in_sizes, int n_in,
                              void* d_out, int out_size)
{
    const float* x    = (const float*)d_in[0];
    const int*   ei   = (const int*)  d_in[1];
    const float* ew   = (const float*)d_in[2];
    const float* lx0i = (const float*)d_in[3];
    const int*   c2o  = (const int*)  d_in[4];
    const int*   lei  = (const int*)  d_in[5];
    const float* lev  = (const float*)d_in[6];
    const int*   midx = (const int*)  d_in[7];
    const int*   mgid = (const int*)  d_in[8];
    const float* Wb    = (const float*)d_in[10];
    const float* bb    = (const float*)d_in[11];
    const float* Wl    = (const float*)d_in[12];
    const float* bl    = (const float*)d_in[13];
    const float* Wbase = (const float*)d_in[14];
    const float* bbase = (const float*)d_in[15];
    const float* Wloc  = (const float*)d_in[16];
    const float* bloc  = (const float*)d_in[17];
    const float* Wp    = (const float*)d_in[18];
    const float* bp    = (const float*)d_in[19];
    float* out = (float*)d_out;

    const int N  = in_sizes[0] / HH;
    const int M  = in_sizes[3] / HH;
    const int E  = in_sizes[1] / 2;
    const int EL = in_sizes[5] / 2;
    const int K  = in_sizes[7];
    const int L  = in_sizes[14] / (HH * HH);

    if (!g_s1) {
        cudaStreamCreateWithFlags(&g_s1, cudaStreamNonBlocking);
        for (int i = 0; i < 8; i++)
            cudaEventCreateWithFlags(&g_ev[i], cudaEventDisableTiming);
    }
    cudaStream_t D = 0, S = g_s1;

    float *bx0, *bx1, *bagg, *lxA, *lxB, *lagg, *sub, *cntp;
    cudaGetSymbolAddress((void**)&bx0,  g_base_x0);
    cudaGetSymbolAddress((void**)&bx1,  g_base_x1);
    cudaGetSymbolAddress((void**)&bagg, g_base_agg);
    cudaGetSymbolAddress((void**)&lxA,  g_local_x0);
    cudaGetSymbolAddress((void**)&lxB,  g_local_x1);
    cudaGetSymbolAddress((void**)&lagg, g_local_agg);
    cudaGetSymbolAddress((void**)&sub,  g_sub);
    cudaGetSymbolAddress((void**)&cntp, g_cnt);

    __nv_bfloat16 *bxb0, *bxb1, *lxbA, *lxbB;
    cudaGetSymbolAddress((void**)&bxb0, g_base_xb0);
    cudaGetSymbolAddress((void**)&bxb1, g_base_xb1);
    cudaGetSymbolAddress((void**)&lxbA, g_local_xb0);
    cudaGetSymbolAddress((void**)&lxbB, g_local_xb1);

    int *csr_cnt, *csr_ptr, *csr_fill, *csr_src, *chunks;
    float* csr_w;
    cudaGetSymbolAddress((void**)&csr_cnt,  g_csr_cnt);
    cudaGetSymbolAddress((void**)&csr_ptr,  g_csr_ptr);
    cudaGetSymbolAddress((void**)&csr_fill, g_csr_fill);
    cudaGetSymbolAddress((void**)&csr_src,  g_csr_src);
    cudaGetSymbolAddress((void**)&csr_w,    g_csr_w);
    cudaGetSymbolAddress((void**)&chunks,   g_chunks);

    int*   ptr_b  = csr_ptr;            int*   ptr_l  = csr_ptr + (NN + 1);
    int*   fill_b = csr_fill;           int*   fill_l = csr_fill + NN;
    int*   src_b  = csr_src;            int*   src_l  = csr_src + EMAX;
    float* w_b    = csr_w;              float* w_l    = csr_w + EMAX;

    cudaFuncSetAttribute(gemm128_bias_relu<false>,
                         cudaFuncAttributeMaxDynamicSharedMemorySize, (int)GEMM_SMEM);
    cudaFuncSetAttribute(gemm128_bias_relu<true>,
                         cudaFuncAttributeMaxDynamicSharedMemorySize, (int)GEMM_SMEM);

    const int tiles_N = N / 64;
    const int tiles_M = M / 64;
    const int ET = E + EL;
    const int etb = (ET + 255) / 256;
    // half-warp per row: n/2 warps -> n*16 threads
    const int spmm_blocks_N = (N * 16 + 255) / 256;
    const int spmm_blocks_M = (M * 16 + 255) / 256;

    // ---- fork S from D ----
    cudaEventRecord(g_ev[0], D);
    cudaStreamWaitEvent(S, g_ev[0], 0);

    // ---- S: input projections ----
    gemm128_bias_relu<false><<<GEMM_GRID, 256, GEMM_SMEM, S>>>(
        x,    Wb, bb, bx0, bxb0, nullptr, nullptr, tiles_N);
    cudaEventRecord(g_ev[1], S);   // base_x0 (+bf16) ready
    gemm128_bias_relu<false><<<GEMM_GRID, 256, GEMM_SMEM, S>>>(
        lx0i, Wl, bl, lxA, lxbA, nullptr, nullptr, tiles_M);

    // ---- D: CSR build, both graphs fused per phase ----
    cudaMemsetAsync(csr_cnt,  0, 2 * NN * sizeof(int), D);
    cudaMemsetAsync(csr_fill, 0, 2 * NN * sizeof(int), D);
    hist2_kernel<<<etb, 256, 0, D>>>(ei + E, E, lei + EL, EL, csr_cnt);
    chunksum_kernel<<<512, 256, 0, D>>>(csr_cnt, chunks);
    scan2_kernel<<<2, 256, 0, D>>>(chunks, ptr_b, ptr_l, N);
    write_ptr2_kernel<<<512, 256, 0, D>>>(csr_cnt, chunks, ptr_b, ptr_l);
    scatter2_kernel<<<etb, 256, 0, D>>>(ei, E, ew, lei, EL, lev,
                                        ptr_b, fill_b, src_b, w_b,
                                        ptr_l, fill_l, src_l, w_l);
    cudaEventRecord(g_ev[2], D);   // both CSRs ready

    cudaStreamWaitEvent(S, g_ev[2], 0);   // S needs local CSR
    cudaStreamWaitEvent(D, g_ev[1], 0);   // D needs base_x0

    // ---- layer loop: base chain on D, local chain on S ----
    float* b_in = bx0;  float* b_out = bx1;
    float* l_in = lxA;  float* l_out = lxB;
    __nv_bfloat16* bb_in = bxb0;  __nv_bfloat16* bb_out = bxb1;
    __nv_bfloat16* lb_in = lxbA;  __nv_bfloat16* lb_out = lxbB;
    for (int l = 0; l < L; l++) {
        spmm_csr<<<spmm_blocks_N, 256, 0, D>>>(bb_in, ptr_b, src_b, w_b, bagg, N);
        gemm128_bias_relu<false><<<GEMM_GRID, 256, GEMM_SMEM, D>>>(
            bagg, Wbase + (size_t)l * HH * HH, bbase + (size_t)l * HH, b_out, bb_out,
            nullptr, nullptr, tiles_N);
        cudaEventRecord(g_ev[4 + l], D);

        spmm_csr<<<spmm_blocks_M, 256, 0, S>>>(lb_in, ptr_l, src_l, w_l, lagg, M);
        cudaStreamWaitEvent(S, g_ev[4 + l], 0);
        gemm128_bias_relu<true><<<GEMM_GRID, 256, GEMM_SMEM, S>>>(
            lagg, Wloc + (size_t)l * HH * HH, bloc + (size_t)l * HH, l_out, lb_out,
            b_out, c2o, tiles_M);

        float* t;
        t = b_in; b_in = b_out; b_out = t;
        t = l_in; l_in = l_out; l_out = t;
        __nv_bfloat16* tb;
        tb = bb_in; bb_in = bb_out; bb_out = tb;
        tb = lb_in; lb_in = lb_out; lb_out = tb;
    }

    // ---- S: pooling + final projection ----
    cudaMemsetAsync(sub,  0, BB * HH * sizeof(float), S);
    cudaMemsetAsync(cntp, 0, BB * sizeof(float), S);
    const int pool_blocks = 128;
    const int entries_per_block = (K + pool_blocks - 1) / pool_blocks;
    pool_kernel<<<pool_blocks, 256, 0, S>>>(l_in, midx, mgid, sub, cntp, K, entries_per_block);
    final_kernel<<<1, 128, 0, S>>>(sub, cntp, Wp, bp, out);

    // ---- join ----
    cudaEventRecord(g_ev[7], S);
    cudaStreamWaitEvent(D, g_ev[7], 0);
}